// round 8
// baseline (speedup 1.0000x reference)
#include <cuda_runtime.h>
#include <cuda_fp16.h>

#define NN 50000
#define DD 64
#define EE 800000

// ---- scratch (device globals; no runtime allocation allowed) ----
__device__ __half2 g_hh[4ull * NN * 32];     // 25.6 MB  h = x@W per param set (fp16)
__device__ float   g_s[4 * NN];              // per-node src score  s_i = h_i . a_src
__device__ float   g_d[4 * NN];              // per-node dst score
__device__ int     g_cnt[8 * NN];            // per-(conv,node) incoming-edge count
__device__ int     g_ebuf[8ull * NN * 64];   // 102.4 MB  src-only records, 64 slots/node

// conv c (edge input order: tp_a,tp_b,tn_a,tn_b,dp_a,dp_b,dn_a,dn_b) -> output slot
static const int h_omap[8] = {0, 1, 4, 5, 2, 3, 6, 7};

// ---------------------------------------------------------------------------
// Kernel 0: zero the per-(conv,node) counters (int4).  grid=391, block=256.
// ---------------------------------------------------------------------------
__global__ void zero_kernel() {
    int z = blockIdx.x * blockDim.x + threadIdx.x;
    if (z < 2 * NN) ((int4*)g_cnt)[z] = make_int4(0, 0, 0, 0);
}

// ---------------------------------------------------------------------------
// Kernel 1: h = x @ W[p] (fp16 out) + fused per-row scores s,d.
// block = 256 (8 warps), 64 rows/block, warp -> 8 rows, lane -> cols {2l,2l+1}.
// grid = (782, 4).  Runs first on the consumer stream, overlapped with scatters.
// ---------------------------------------------------------------------------
__global__ void __launch_bounds__(256) gemm_kernel(const float* __restrict__ x,
                                                   const float* __restrict__ W,
                                                   const float* __restrict__ asrc,
                                                   const float* __restrict__ adst) {
    __shared__ float Ws[64 * 64];            // 16 KB
    __shared__ float xs[64 * 68];            // 17.4 KB (68-stride: float4-aligned + pad)
    const int p    = blockIdx.y;
    const int row0 = blockIdx.x * 64;
    const int tid  = threadIdx.x;

    {   // load W (1024 float4, coalesced)
        const float4* W4 = (const float4*)(W + p * 4096);
        float4* Ws4 = (float4*)Ws;
        Ws4[tid]       = W4[tid];
        Ws4[tid + 256] = W4[tid + 256];
        Ws4[tid + 512] = W4[tid + 512];
        Ws4[tid + 768] = W4[tid + 768];
    }
    // load 64 x-rows (float4, coalesced)
#pragma unroll
    for (int q = tid; q < 1024; q += 256) {
        int r = q >> 4, c4 = q & 15;
        int grow = row0 + r;
        float4 v = (grow < NN) ? ((const float4*)x)[(size_t)grow * 16 + c4]
                               : make_float4(0.f, 0.f, 0.f, 0.f);
        *(float4*)&xs[r * 68 + c4 * 4] = v;
    }
    __syncthreads();

    const int warp = tid >> 5, lane = tid & 31;
    const int r0 = warp * 8;
    float2 acc[8];
#pragma unroll
    for (int r = 0; r < 8; r++) acc[r] = make_float2(0.f, 0.f);

    const float2* Ws2 = (const float2*)Ws;
#pragma unroll 4
    for (int k = 0; k < 64; k += 4) {
        float2 w0 = Ws2[(k + 0) * 32 + lane];
        float2 w1 = Ws2[(k + 1) * 32 + lane];
        float2 w2 = Ws2[(k + 2) * 32 + lane];
        float2 w3 = Ws2[(k + 3) * 32 + lane];
#pragma unroll
        for (int r = 0; r < 8; r++) {
            float4 xv = *(const float4*)&xs[(r0 + r) * 68 + k];
            acc[r].x = fmaf(xv.x, w0.x, acc[r].x); acc[r].y = fmaf(xv.x, w0.y, acc[r].y);
            acc[r].x = fmaf(xv.y, w1.x, acc[r].x); acc[r].y = fmaf(xv.y, w1.y, acc[r].y);
            acc[r].x = fmaf(xv.z, w2.x, acc[r].x); acc[r].y = fmaf(xv.z, w2.y, acc[r].y);
            acc[r].x = fmaf(xv.w, w3.x, acc[r].x); acc[r].y = fmaf(xv.w, w3.y, acc[r].y);
        }
    }

    // fused scores: s = h.a_src, d = h.a_dst via in-warp butterfly reduce
    float2 av = ((const float2*)(asrc + p * 64))[lane];
    float2 bv = ((const float2*)(adst + p * 64))[lane];
    __half2* hp = g_hh + (size_t)p * NN * 32;

#pragma unroll
    for (int r = 0; r < 8; r++) {
        int grow = row0 + r0 + r;
        float sv = acc[r].x * av.x + acc[r].y * av.y;
        float dv = acc[r].x * bv.x + acc[r].y * bv.y;
#pragma unroll
        for (int off = 16; off; off >>= 1) {
            sv += __shfl_xor_sync(0xffffffffu, sv, off);
            dv += __shfl_xor_sync(0xffffffffu, dv, off);
        }
        if (grow < NN) {
            hp[(size_t)grow * 32 + lane] = __float22half2_rn(acc[r]);  // 128B/row
            if (lane == 0) { g_s[p * NN + grow] = sv; g_d[p * NN + grow] = dv; }
        }
    }
}

// ---------------------------------------------------------------------------
// Kernel 2: per-conv scatter. 4 edges/thread via int4 loads (4 independent
// atomic->store chains per thread).  grid = 782, block = 256.
// ---------------------------------------------------------------------------
__global__ void __launch_bounds__(256) scatter_kernel(const int* __restrict__ e, int c) {
    const int r4 = blockIdx.x * blockDim.x + threadIdx.x;   // quad index
    if (r4 * 4 >= EE) return;
    int4 sv = __ldg((const int4*)e + r4);
    int4 dv = __ldg((const int4*)(e + EE) + r4);
    int* cnt = g_cnt + c * NN;
    int* ebc = g_ebuf + (((size_t)c * NN) << 6);
    if (sv.x != dv.x) {                     // ref masks self edges -> weight 0
        int sl = atomicAdd(cnt + dv.x, 1);
        if (sl < 64) ebc[((size_t)dv.x << 6) + sl] = sv.x;
    }
    if (sv.y != dv.y) {
        int sl = atomicAdd(cnt + dv.y, 1);
        if (sl < 64) ebc[((size_t)dv.y << 6) + sl] = sv.y;
    }
    if (sv.z != dv.z) {
        int sl = atomicAdd(cnt + dv.z, 1);
        if (sl < 64) ebc[((size_t)dv.z << 6) + sl] = sv.z;
    }
    if (sv.w != dv.w) {
        int sl = atomicAdd(cnt + dv.w, 1);
        if (sl < 64) ebc[((size_t)dv.w << 6) + sl] = sv.w;
    }
}

// ---------------------------------------------------------------------------
// Kernel 3: per-conv gather. Warp per node, 4 nodes per warp (grid-stride);
// weights lane-parallel (MUFU exp); records padded with zero weights ->
// unguarded pairwise loop via LDS.128; dual accumulators for ILP.
// grid = 3125, block = 128 (4 warps).
// ---------------------------------------------------------------------------
__global__ void __launch_bounds__(128) gather_kernel(const float* __restrict__ bias,
                                                     float* __restrict__ out,
                                                     int c, int p, int o) {
    __shared__ int2 rec[4][64];
    const int warp = threadIdx.x >> 5, lane = threadIdx.x & 31;
    const int nwarps = gridDim.x * 4;                       // 12500
    const int wg0 = blockIdx.x * 4 + warp;

    const float*   sp  = g_s + p * NN;
    const float*   dp  = g_d + p * NN;
    const __half2* hb  = g_hh + (size_t)p * NN * 32 + lane; // per-thread base
    const int*     cnc = g_cnt + c * NN;
    const int*     ebc = g_ebuf + (((size_t)c * NN) << 6);
    float2 bb = ((const float2*)bias)[p * 32 + lane];
    float2* outp = (float2*)out + (size_t)o * NN * 32 + lane;

    for (int i = wg0; i < NN; i += nwarps) {
        int n = cnc[i];
        if (n > 64) n = 64;
        const int* eb = ebc + ((size_t)i << 6);
        const float d_i = __ldg(dp + i);

        float w1 = 0.f, w2 = 0.f;
        int   s1 = 0,   s2 = 0;
        if (lane < n) {
            s1 = __ldg(eb + lane);
            float t = __ldg(sp + s1) + d_i;
            t = t > 0.f ? t : 0.2f * t;
            w1 = __expf(t);
        }
        if (lane + 32 < n) {
            s2 = __ldg(eb + lane + 32);
            float t = __ldg(sp + s2) + d_i;
            t = t > 0.f ? t : 0.2f * t;
            w2 = __expf(t);
        }
        __syncwarp();                       // rec reads of previous node done
        rec[warp][lane]      = make_int2(s1, __float_as_int(w1));
        rec[warp][lane + 32] = make_int2(s2, __float_as_int(w2));
        __syncwarp();

        float tself = __ldg(sp + i) + d_i;
        tself = tself > 0.f ? tself : 0.2f * tself;
        const float wself = __expf(tself);

        float wsum = w1 + w2;
#pragma unroll
        for (int off = 16; off; off >>= 1) wsum += __shfl_xor_sync(0xffffffffu, wsum, off);
        const float inv = 1.f / (wself + wsum);

        float2 hv = __half22float2(hb[(size_t)i * 32]);
        float ax0 = wself * hv.x, ay0 = wself * hv.y;
        float ax1 = 0.f, ay1 = 0.f;

        const int4* rp = (const int4*)rec[warp];            // 2 records per int4
        const int n2 = (n + 1) >> 1;
#pragma unroll 2
        for (int kk = 0; kk < n2; kk++) {
            int4 rr = rp[kk];                               // LDS.128 broadcast
            float2 h0 = __half22float2(__ldg(hb + (size_t)rr.x * 32));
            float2 h1 = __half22float2(__ldg(hb + (size_t)rr.z * 32));
            float wa = __int_as_float(rr.y), wb2 = __int_as_float(rr.w);
            ax0 = fmaf(wa,  h0.x, ax0); ay0 = fmaf(wa,  h0.y, ay0);
            ax1 = fmaf(wb2, h1.x, ax1); ay1 = fmaf(wb2, h1.y, ay1);
        }

        float ax = fmaxf(fmaf(ax0 + ax1, inv, bb.x), 0.f);
        float ay = fmaxf(fmaf(ay0 + ay1, inv, bb.y), 0.f);
        outp[(size_t)i * 32] = make_float2(ax, ay);
    }
}

// ---------------------------------------------------------------------------
// Launch choreography: TWO streams only (round-5-proven skeleton + per-conv
// events crossing one way, main -> side).
//   stream 0  : zero -> scatter_0..7   (producer chain; records evS[c])
//   sCons     : gemm -> gather_0..7    (consumer chain; waits evS[c])
//   join      : evJoin (sCons) -> stream 0
// ---------------------------------------------------------------------------
extern "C" void kernel_launch(void* const* d_in, const int* in_sizes, int n_in,
                              void* d_out, int out_size) {
    (void)in_sizes; (void)n_in; (void)out_size;
    const float* x    = (const float*)d_in[8];
    const float* W    = (const float*)d_in[9];
    const float* asrc = (const float*)d_in[10];
    const float* adst = (const float*)d_in[11];
    const float* bias = (const float*)d_in[12];

    static cudaStream_t sCons = nullptr;
    static cudaEvent_t evFork = nullptr, evJoin = nullptr, evS[8];
    if (!sCons) {
        cudaStreamCreateWithFlags(&sCons, cudaStreamNonBlocking);
        cudaEventCreateWithFlags(&evFork, cudaEventDisableTiming);
        cudaEventCreateWithFlags(&evJoin, cudaEventDisableTiming);
        for (int i = 0; i < 8; i++) cudaEventCreateWithFlags(&evS[i], cudaEventDisableTiming);
    }

    // fork consumer stream off the capture origin
    cudaEventRecord(evFork, 0);
    cudaStreamWaitEvent(sCons, evFork, 0);

    // consumer chain head: gemm (+scores) — independent of scatters
    dim3 ggrid((NN + 63) / 64, 4);
    gemm_kernel<<<ggrid, 256, 0, sCons>>>(x, W, asrc, adst);

    // producer chain on main stream: zero, then per-conv scatters
    zero_kernel<<<(2 * NN + 255) / 256, 256>>>();
    for (int c = 0; c < 8; c++) {
        scatter_kernel<<<(EE / 4 + 255) / 256, 256>>>((const int*)d_in[c], c);
        cudaEventRecord(evS[c], 0);
    }

    // consumer chain tail: per-conv gathers, each gated only on its scatter
    for (int c = 0; c < 8; c++) {
        cudaStreamWaitEvent(sCons, evS[c], 0);
        gather_kernel<<<3125, 128, 0, sCons>>>(bias, (float*)d_out, c, c >> 1, h_omap[c]);
    }

    // join back to capture origin
    cudaEventRecord(evJoin, sCons);
    cudaStreamWaitEvent(0, evJoin, 0);
}

// round 9
// speedup vs baseline: 1.2142x; 1.2142x over previous
#include <cuda_runtime.h>
#include <cuda_fp16.h>

#define NN 50000
#define DD 64
#define EE 800000

// ---- scratch (device globals; no runtime allocation allowed) ----
__device__ __half2 g_hh[4ull * NN * 32];     // 25.6 MB  h = x@W per param set (fp16)
__device__ float   g_s[4 * NN];              // per-node src score  s_i = h_i . a_src
__device__ float   g_d[4 * NN];              // per-node dst score
__device__ int     g_cnt[8 * NN];            // per-(conv,node) incoming-edge count
__device__ int     g_ebuf[8ull * NN * 64];   // 102.4 MB  src-only records, 64 slots/node

// conv c (edge input order: tp_a,tp_b,tn_a,tn_b,dp_a,dp_b,dn_a,dn_b) -> output slot
__constant__ int c_omap[8] = {0, 1, 4, 5, 2, 3, 6, 7};

struct EdgePtrs { const int* e[8]; };

// ---------------------------------------------------------------------------
// Kernel 0: zero the per-(conv,node) counters (int4).  grid=391, block=256.
// ---------------------------------------------------------------------------
__global__ void zero_kernel() {
    int z = blockIdx.x * blockDim.x + threadIdx.x;
    if (z < 2 * NN) ((int4*)g_cnt)[z] = make_int4(0, 0, 0, 0);
}

// ---------------------------------------------------------------------------
// Kernel 1: h = x @ W[p] (fp16 out) + fused per-row scores s,d.
// block = 256 (8 warps), 64 rows/block, warp -> 8 rows, lane -> cols {2l,2l+1}.
// grid = (782, 4).  Runs on the side stream, overlapped with zero+scatter.
// ---------------------------------------------------------------------------
__global__ void __launch_bounds__(256) gemm_kernel(const float* __restrict__ x,
                                                   const float* __restrict__ W,
                                                   const float* __restrict__ asrc,
                                                   const float* __restrict__ adst) {
    __shared__ float Ws[64 * 64];            // 16 KB
    __shared__ float xs[64 * 68];            // 17.4 KB (68-stride: float4-aligned + pad)
    const int p    = blockIdx.y;
    const int row0 = blockIdx.x * 64;
    const int tid  = threadIdx.x;

    {   // load W (1024 float4, coalesced)
        const float4* W4 = (const float4*)(W + p * 4096);
        float4* Ws4 = (float4*)Ws;
        Ws4[tid]       = W4[tid];
        Ws4[tid + 256] = W4[tid + 256];
        Ws4[tid + 512] = W4[tid + 512];
        Ws4[tid + 768] = W4[tid + 768];
    }
    // load 64 x-rows (float4, coalesced)
#pragma unroll
    for (int q = tid; q < 1024; q += 256) {
        int r = q >> 4, c4 = q & 15;
        int grow = row0 + r;
        float4 v = (grow < NN) ? ((const float4*)x)[(size_t)grow * 16 + c4]
                               : make_float4(0.f, 0.f, 0.f, 0.f);
        *(float4*)&xs[r * 68 + c4 * 4] = v;
    }
    __syncthreads();

    const int warp = tid >> 5, lane = tid & 31;
    const int r0 = warp * 8;
    float2 acc[8];
#pragma unroll
    for (int r = 0; r < 8; r++) acc[r] = make_float2(0.f, 0.f);

    const float2* Ws2 = (const float2*)Ws;
#pragma unroll 4
    for (int k = 0; k < 64; k += 4) {
        float2 w0 = Ws2[(k + 0) * 32 + lane];
        float2 w1 = Ws2[(k + 1) * 32 + lane];
        float2 w2 = Ws2[(k + 2) * 32 + lane];
        float2 w3 = Ws2[(k + 3) * 32 + lane];
#pragma unroll
        for (int r = 0; r < 8; r++) {
            float4 xv = *(const float4*)&xs[(r0 + r) * 68 + k];
            acc[r].x = fmaf(xv.x, w0.x, acc[r].x); acc[r].y = fmaf(xv.x, w0.y, acc[r].y);
            acc[r].x = fmaf(xv.y, w1.x, acc[r].x); acc[r].y = fmaf(xv.y, w1.y, acc[r].y);
            acc[r].x = fmaf(xv.z, w2.x, acc[r].x); acc[r].y = fmaf(xv.z, w2.y, acc[r].y);
            acc[r].x = fmaf(xv.w, w3.x, acc[r].x); acc[r].y = fmaf(xv.w, w3.y, acc[r].y);
        }
    }

    // fused scores: s = h.a_src, d = h.a_dst via in-warp butterfly reduce
    float2 av = ((const float2*)(asrc + p * 64))[lane];
    float2 bv = ((const float2*)(adst + p * 64))[lane];
    __half2* hp = g_hh + (size_t)p * NN * 32;

#pragma unroll
    for (int r = 0; r < 8; r++) {
        int grow = row0 + r0 + r;
        float sv = acc[r].x * av.x + acc[r].y * av.y;
        float dv = acc[r].x * bv.x + acc[r].y * bv.y;
#pragma unroll
        for (int off = 16; off; off >>= 1) {
            sv += __shfl_xor_sync(0xffffffffu, sv, off);
            dv += __shfl_xor_sync(0xffffffffu, dv, off);
        }
        if (grow < NN) {
            hp[(size_t)grow * 32 + lane] = __float22half2_rn(acc[r]);  // 128B/row
            if (lane == 0) { g_s[p * NN + grow] = sv; g_d[p * NN + grow] = dv; }
        }
    }
}

// ---------------------------------------------------------------------------
// Kernel 2: ALL-conv scatter in one launch (blockIdx.y = conv). 4 edges/thread
// via int4 -> 4 independent atomic chains/thread, 8 convs concurrently for MLP.
// grid = (782, 8), block = 256.
// ---------------------------------------------------------------------------
__global__ void __launch_bounds__(256) scatter_kernel(EdgePtrs ep) {
    const int c  = blockIdx.y;
    const int r4 = blockIdx.x * blockDim.x + threadIdx.x;   // quad index
    if (r4 * 4 >= EE) return;
    const int* __restrict__ e = ep.e[c];
    int4 sv = __ldg((const int4*)e + r4);
    int4 dv = __ldg((const int4*)(e + EE) + r4);
    int* cnt = g_cnt + c * NN;
    int* ebc = g_ebuf + (((size_t)c * NN) << 6);
    if (sv.x != dv.x) {                     // ref masks self edges -> weight 0
        int sl = atomicAdd(cnt + dv.x, 1);
        if (sl < 64) ebc[((size_t)dv.x << 6) + sl] = sv.x;
    }
    if (sv.y != dv.y) {
        int sl = atomicAdd(cnt + dv.y, 1);
        if (sl < 64) ebc[((size_t)dv.y << 6) + sl] = sv.y;
    }
    if (sv.z != dv.z) {
        int sl = atomicAdd(cnt + dv.z, 1);
        if (sl < 64) ebc[((size_t)dv.z << 6) + sl] = sv.z;
    }
    if (sv.w != dv.w) {
        int sl = atomicAdd(cnt + dv.w, 1);
        if (sl < 64) ebc[((size_t)dv.w << 6) + sl] = sv.w;
    }
}

// ---------------------------------------------------------------------------
// Kernel 3: ALL-conv gather (blockIdx.y = conv). Warp per node, 4 nodes/warp
// grid-stride. HALF-WARP per edge: lane covers 4 cols (LDG.64 of 2x half2),
// warp does 2 edges/iter; half-warp partials combined by 4 shfl at the end.
// Upper record slots only touched when n > 32 (rare).  grid = (3125, 8),
// block = 128 (4 warps).
// ---------------------------------------------------------------------------
__global__ void __launch_bounds__(128) gather_kernel(const float* __restrict__ bias,
                                                     float* __restrict__ out) {
    __shared__ int2 rec[4][64];
    const int c    = blockIdx.y;
    const int p    = c >> 1;
    const int o    = c_omap[c];
    const int warp = threadIdx.x >> 5, lane = threadIdx.x & 31;
    const int half = lane >> 4, l16 = lane & 15;
    const int wg0  = blockIdx.x * 4 + warp;               // 12500 warps / conv

    const float* sp  = g_s + p * NN;
    const float* dp  = g_d + p * NN;
    const int*   cnc = g_cnt + c * NN;
    const int*   ebc = g_ebuf + (((size_t)c * NN) << 6);
    // lane's 4 columns = one uint2 (2 x half2) at half2-offset 2*l16 of the row
    const uint2* hb  = (const uint2*)(g_hh + (size_t)p * NN * 32) + l16;
    float4 bb = ((const float4*)(bias + p * 64))[l16];
    float4* outp = (float4*)out + (size_t)o * NN * 16 + l16;

    for (int i = wg0; i < NN; i += 12500) {
        int n = cnc[i];
        if (n > 64) n = 64;
        const int* eb = ebc + ((size_t)i << 6);
        const float d_i = __ldg(dp + i);

        // per-slot weights (lane-parallel exp); upper 32 slots only if needed
        float w1 = 0.f, w2 = 0.f;
        int   s1 = 0;
        if (lane < n) {
            s1 = __ldg(eb + lane);
            float t = __ldg(sp + s1) + d_i;
            t = t > 0.f ? t : 0.2f * t;
            w1 = __expf(t);
        }
        __syncwarp();                                     // prev node's reads done
        rec[warp][lane] = make_int2(s1, __float_as_int(w1));
        if (n > 32) {
            int s2 = 0;
            if (lane + 32 < n) {
                s2 = __ldg(eb + lane + 32);
                float t = __ldg(sp + s2) + d_i;
                t = t > 0.f ? t : 0.2f * t;
                w2 = __expf(t);
            }
            rec[warp][lane + 32] = make_int2(s2, __float_as_int(w2));
        }
        __syncwarp();

        float tself = __ldg(sp + i) + d_i;
        tself = tself > 0.f ? tself : 0.2f * tself;
        const float wself = __expf(tself);

        float wsum = w1 + w2;
#pragma unroll
        for (int off = 16; off; off >>= 1) wsum += __shfl_xor_sync(0xffffffffu, wsum, off);
        const float inv = 1.f / (wself + wsum);

        // self contribution: only lower half-warp accumulates it (avoid x2)
        uint2 hs = __ldg(hb + (size_t)i * 16);
        float2 f0 = __half22float2(*(__half2*)&hs.x);
        float2 f1 = __half22float2(*(__half2*)&hs.y);
        const float ws0 = half ? 0.f : wself;
        float a0 = ws0 * f0.x, a1 = ws0 * f0.y, a2 = ws0 * f1.x, a3 = ws0 * f1.y;

        // 2 edges per warp-iteration: half-warp h handles slot 2*kk+h
        const int niter = (n + 1) >> 1;
        const int2* rp = rec[warp] + half;
        for (int kk = 0; kk < niter; kk++) {
            int2 rr = rp[2 * kk];                         // LDS.64, 2-addr broadcast
            uint2 hv = __ldg(hb + (size_t)rr.x * 16);
            float wk = __int_as_float(rr.y);
            float2 g0 = __half22float2(*(__half2*)&hv.x);
            float2 g1 = __half22float2(*(__half2*)&hv.y);
            a0 = fmaf(wk, g0.x, a0); a1 = fmaf(wk, g0.y, a1);
            a2 = fmaf(wk, g1.x, a2); a3 = fmaf(wk, g1.y, a3);
        }

        // combine the two half-warp partials (cols identical across halves)
        a0 += __shfl_xor_sync(0xffffffffu, a0, 16);
        a1 += __shfl_xor_sync(0xffffffffu, a1, 16);
        a2 += __shfl_xor_sync(0xffffffffu, a2, 16);
        a3 += __shfl_xor_sync(0xffffffffu, a3, 16);

        if (lane < 16) {
            float4 r;
            r.x = fmaxf(fmaf(a0, inv, bb.x), 0.f);
            r.y = fmaxf(fmaf(a1, inv, bb.y), 0.f);
            r.z = fmaxf(fmaf(a2, inv, bb.z), 0.f);
            r.w = fmaxf(fmaf(a3, inv, bb.w), 0.f);
            outp[(size_t)i * 16] = r;                     // 256B coalesced row
        }
    }
}

// ---------------------------------------------------------------------------
// Choreography: round-5-proven two-stream fork/join, monolithic launches.
//   sCons   : gemm (+scores)          -> evJoin
//   stream0 : zero -> scatterAll ; wait evJoin ; gatherAll
// ---------------------------------------------------------------------------
extern "C" void kernel_launch(void* const* d_in, const int* in_sizes, int n_in,
                              void* d_out, int out_size) {
    (void)in_sizes; (void)n_in; (void)out_size;
    const float* x    = (const float*)d_in[8];
    const float* W    = (const float*)d_in[9];
    const float* asrc = (const float*)d_in[10];
    const float* adst = (const float*)d_in[11];
    const float* bias = (const float*)d_in[12];

    EdgePtrs ep;
    for (int i = 0; i < 8; i++) ep.e[i] = (const int*)d_in[i];

    static cudaStream_t sCons = nullptr;
    static cudaEvent_t evFork = nullptr, evJoin = nullptr;
    if (!sCons) {
        cudaStreamCreateWithFlags(&sCons, cudaStreamNonBlocking);
        cudaEventCreateWithFlags(&evFork, cudaEventDisableTiming);
        cudaEventCreateWithFlags(&evJoin, cudaEventDisableTiming);
    }

    // fork: gemm (+scores) on side stream
    cudaEventRecord(evFork, 0);
    cudaStreamWaitEvent(sCons, evFork, 0);
    dim3 ggrid((NN + 63) / 64, 4);
    gemm_kernel<<<ggrid, 256, 0, sCons>>>(x, W, asrc, adst);
    cudaEventRecord(evJoin, sCons);

    // main: zero + all-conv scatter
    zero_kernel<<<(2 * NN + 255) / 256, 256>>>();
    dim3 sgrid((EE / 4 + 255) / 256, 8);
    scatter_kernel<<<sgrid, 256>>>(ep);

    // join, then all-conv gather
    cudaStreamWaitEvent(0, evJoin, 0);
    dim3 agrid(3125, 8);
    gather_kernel<<<agrid, 128>>>(bias, (float*)d_out);
}